// round 7
// baseline (speedup 1.0000x reference)
#include <cuda_runtime.h>
#include <cuda_bf16.h>
#include <cuda_fp16.h>
#include <cstdint>

#define N_NODES  100000
#define N_PAD    100096          // 782 * 128
#define N_EDGES  1600000
#define N_GRAPHS 100
#define SCAN_B   1024
#define NB_SCAN  98

// ---------------- scratch (static __device__ allocations only) ----------------
__device__ __nv_bfloat16 g_ah[N_PAD * 128];   // A hi plane (pitch 128)
__device__ __nv_bfloat16 g_al[N_PAD * 128];   // A lo plane
__device__ __nv_bfloat16 g_bh[256 * 128];     // B hi plane [n][k]
__device__ __nv_bfloat16 g_bl[256 * 128];     // B lo plane
__device__ __half g_yn[N_PAD * 128];          // neighbor-transform out (fp16, pitch 128)
__device__ float  g_ys[N_PAD * 128];          // self-transform out (fp32, pitch 128)
__device__ float  g_h3[N_NODES * 104];        // layer-3 activation (fp32, pitch 104)
__device__ float  g_h4[N_NODES * 8];          // final node features (pitch 8)
__device__ float g_invdeg[N_NODES];
__device__ int   g_rowcnt[N_NODES];
__device__ int   g_rowptr[N_NODES];
__device__ int   g_cursor[N_NODES];
__device__ int   g_csr[N_EDGES];
__device__ int   g_bsum[128];
__device__ int   g_boff[128];
__device__ float g_pool[N_GRAPHS * 5];
__device__ int   g_gcnt[N_GRAPHS];

// ---------------- PTX helpers ----------------
__device__ __forceinline__ uint32_t smem_u32(const void* p) {
    uint32_t a;
    asm("{ .reg .u64 t; cvta.to.shared.u64 t, %1; cvt.u32.u64 %0, t; }" : "=r"(a) : "l"(p));
    return a;
}
__device__ __forceinline__ void ldsm4(uint32_t* r, uint32_t addr) {
    asm volatile("ldmatrix.sync.aligned.m8n8.x4.shared.b16 {%0,%1,%2,%3}, [%4];"
                 : "=r"(r[0]), "=r"(r[1]), "=r"(r[2]), "=r"(r[3]) : "r"(addr));
}
__device__ __forceinline__ void mma16816(float* c, const uint32_t* a,
                                         uint32_t b0, uint32_t b1) {
    asm volatile(
        "mma.sync.aligned.m16n8k16.row.col.f32.bf16.bf16.f32 "
        "{%0,%1,%2,%3}, {%4,%5,%6,%7}, {%8,%9}, {%0,%1,%2,%3};"
        : "+f"(c[0]), "+f"(c[1]), "+f"(c[2]), "+f"(c[3])
        : "r"(a[0]), "r"(a[1]), "r"(a[2]), "r"(a[3]), "r"(b0), "r"(b1));
}
__device__ __forceinline__ void cpa16(uint32_t d, const void* g) {
    asm volatile("cp.async.cg.shared.global [%0], [%1], 16;" :: "r"(d), "l"(g));
}
__device__ __forceinline__ void cp_commit() {
    asm volatile("cp.async.commit_group;" ::: "memory");
}
template<int N> __device__ __forceinline__ void cp_wait() {
    asm volatile("cp.async.wait_group %0;" :: "n"(N) : "memory");
}

// ---------------- CSR build ----------------
__global__ void k_zero() {
    int i = blockIdx.x * blockDim.x + threadIdx.x;
    if (i < N_NODES) g_rowcnt[i] = 0;
    if (i < N_GRAPHS * 5) g_pool[i] = 0.f;
    if (i < N_GRAPHS) g_gcnt[i] = 0;
}

__global__ void k_count(const int* __restrict__ dst) {
    int e = blockIdx.x * blockDim.x + threadIdx.x;
    if (e < N_EDGES) atomicAdd(&g_rowcnt[dst[e]], 1);
}

__global__ void k_scan1() {
    __shared__ int s[SCAN_B];
    int tid = threadIdx.x;
    int gid = blockIdx.x * SCAN_B + tid;
    int v = (gid < N_NODES) ? g_rowcnt[gid] : 0;
    s[tid] = v;
    __syncthreads();
    for (int off = 1; off < SCAN_B; off <<= 1) {
        int t = (tid >= off) ? s[tid - off] : 0;
        __syncthreads();
        s[tid] += t;
        __syncthreads();
    }
    if (gid < N_NODES) g_rowptr[gid] = s[tid] - v;
    if (tid == SCAN_B - 1) g_bsum[blockIdx.x] = s[tid];
}

__global__ void k_scan2() {
    __shared__ int s[128];
    int t = threadIdx.x;
    int v = (t < NB_SCAN) ? g_bsum[t] : 0;
    s[t] = v;
    __syncthreads();
    for (int off = 1; off < 128; off <<= 1) {
        int x = (t >= off) ? s[t - off] : 0;
        __syncthreads();
        s[t] += x;
        __syncthreads();
    }
    if (t < NB_SCAN) g_boff[t] = s[t] - v;
}

__global__ void k_scan3() {
    int gid = blockIdx.x * SCAN_B + threadIdx.x;
    if (gid < N_NODES) {
        int rp = g_rowptr[gid] + g_boff[blockIdx.x];
        g_rowptr[gid] = rp;
        g_cursor[gid] = rp;
        int c = g_rowcnt[gid];
        g_invdeg[gid] = 1.0f / (float)(c > 0 ? c : 1);
    }
}

__global__ void k_fill(const int* __restrict__ src, const int* __restrict__ dst) {
    int e = blockIdx.x * blockDim.x + threadIdx.x;
    if (e < N_EDGES) {
        int pos = atomicAdd(&g_cursor[dst[e]], 1);
        g_csr[pos] = src[e];
    }
}

// ---------------- input / weight conversion to bf16 hi/lo ----------------
__device__ __forceinline__ void split_bf(float v, __nv_bfloat16& h, __nv_bfloat16& l) {
    h = __float2bfloat16(v);
    l = __float2bfloat16(v - __bfloat162float(h));
}

__global__ void k_conv_in(const float* __restrict__ x) {
    int idx = blockIdx.x * blockDim.x + threadIdx.x;   // N_PAD*128
    int n = idx >> 7;
    float v = (n < N_NODES) ? x[idx] : 0.f;
    __nv_bfloat16 h, l;
    split_bf(v, h, l);
    g_ah[idx] = h;
    g_al[idx] = l;
}

// B[n][k] = Wn[k][n] (n<128) | Ws[k][n-128], zero-padded
__global__ void k_wconv(const float* __restrict__ Wn, const float* __restrict__ Ws,
                        int K, int dout) {
    int idx = blockIdx.x * blockDim.x + threadIdx.x;   // 256*128
    int n = idx >> 7, k = idx & 127;
    float v = 0.f;
    if (k < K) {
        if (n < 128) { if (n < dout) v = Wn[k * dout + n]; }
        else { int s = n - 128; if (s < dout) v = Ws[k * dout + s]; }
    }
    __nv_bfloat16 h, l;
    split_bf(v, h, l);
    g_bh[idx] = h;
    g_bl[idx] = l;
}

// ---------------- pipelined HMMA GEMM (high arithmetic intensity) ----------------
// Per CTA: 128(m) x 256(n), K=128 in 4 chunks of 32, 2-stage cp.async.
// 8 warps in 2(m) x 4(n); warp tile 64x64 -> 12 FLOP per smem byte.
// Output: n<128 -> Yn fp16 (Wn half), n>=128 -> Ys fp32 (Ws half).
#define PITCH  80                        // 64B data + 16B pad per k32 row
#define APLANE 10240                     // 128 rows * 80
#define BPLANE 20480                     // 256 rows * 80
#define STAGEB 61440                     // 2*APLANE + 2*BPLANE
#define SM_B   20480                     // offset of Bh within stage (2*APLANE)
#define GEMM_SMEM 122880

__global__ void __launch_bounds__(256)
k_gemm_pipe(const __nv_bfloat16* __restrict__ ah, const __nv_bfloat16* __restrict__ al,
            const __nv_bfloat16* __restrict__ bh, const __nv_bfloat16* __restrict__ bl,
            __half* __restrict__ Yn, float* __restrict__ Ys)
{
    extern __shared__ char smem[];
    const int tid = threadIdx.x;
    const int m0 = blockIdx.x * 128;
    const uint32_t sb = smem_u32(smem);

    const int f_row = tid >> 2;          // 64 rows per pass
    const int f_kc  = tid & 3;           // 4 x 16B chunks per row
    #define FILL(st, ks) do {                                                  \
        uint32_t sbase = sb + (st) * STAGEB;                                   \
        _Pragma("unroll")                                                      \
        for (int i = 0; i < 2; ++i) {                                          \
            int row = f_row + i * 64;                                          \
            uint32_t doff = row * PITCH + f_kc * 16;                           \
            size_t ga = (size_t)(m0 + row) * 128 + (ks) * 32 + f_kc * 8;       \
            cpa16(sbase + doff,          ah + ga);                             \
            cpa16(sbase + APLANE + doff, al + ga);                             \
        }                                                                      \
        _Pragma("unroll")                                                      \
        for (int i = 0; i < 4; ++i) {                                          \
            int row = f_row + i * 64;                                          \
            uint32_t doff = row * PITCH + f_kc * 16;                           \
            size_t gb = (size_t)row * 128 + (ks) * 32 + f_kc * 8;              \
            cpa16(sbase + SM_B + doff,          bh + gb);                      \
            cpa16(sbase + SM_B + BPLANE + doff, bl + gb);                      \
        }                                                                      \
    } while (0)

    FILL(0, 0); cp_commit();
    FILL(1, 1); cp_commit();

    const int wid = tid >> 5, lane = tid & 31;
    const int wm  = (wid & 1) * 64;      // warp m offset (2 rows of warps)
    const int wn  = (wid >> 1) * 64;     // warp n offset (4 cols of warps)

    float acc[4][8][4];                  // 4 m16 frags x 8 n8 frags
    #pragma unroll
    for (int mf = 0; mf < 4; ++mf)
        #pragma unroll
        for (int nf = 0; nf < 8; ++nf)
            #pragma unroll
            for (int q = 0; q < 4; ++q) acc[mf][nf][q] = 0.f;

    const uint32_t aL = (uint32_t)(lane & 15) * PITCH + (lane >> 4) * 16;
    const uint32_t bL = (uint32_t)((lane & 7) + ((lane >> 4) << 3)) * PITCH
                        + ((lane >> 3) & 1) * 16;

    #pragma unroll
    for (int ks = 0; ks < 4; ++ks) {
        cp_wait<1>();
        __syncthreads();
        const uint32_t st = sb + (ks & 1) * STAGEB;
        #pragma unroll
        for (int kk = 0; kk < 2; ++kk) {
            const uint32_t kb = kk * 32;
            uint32_t Ah[4][4], Al[4][4], Bh4[4][4], Bl4[4][4];
            #pragma unroll
            for (int mf = 0; mf < 4; ++mf) {
                uint32_t base = st + (uint32_t)(wm + mf * 16) * PITCH + aL + kb;
                ldsm4(Ah[mf], base);
                ldsm4(Al[mf], base + APLANE);
            }
            #pragma unroll
            for (int nq = 0; nq < 4; ++nq) {
                uint32_t bbase = st + SM_B + (uint32_t)(wn + nq * 16) * PITCH + bL + kb;
                ldsm4(Bh4[nq], bbase);
                ldsm4(Bl4[nq], bbase + BPLANE);
            }
            #pragma unroll
            for (int nq = 0; nq < 4; ++nq)
                #pragma unroll
                for (int mf = 0; mf < 4; ++mf) {
                    float* c0 = acc[mf][2 * nq];
                    float* c1 = acc[mf][2 * nq + 1];
                    mma16816(c0, Ah[mf], Bh4[nq][0], Bh4[nq][1]);
                    mma16816(c0, Al[mf], Bh4[nq][0], Bh4[nq][1]);
                    mma16816(c0, Ah[mf], Bl4[nq][0], Bl4[nq][1]);
                    mma16816(c1, Ah[mf], Bh4[nq][2], Bh4[nq][3]);
                    mma16816(c1, Al[mf], Bh4[nq][2], Bh4[nq][3]);
                    mma16816(c1, Ah[mf], Bl4[nq][2], Bl4[nq][3]);
                }
        }
        __syncthreads();
        if (ks + 2 < 4) { FILL(ks & 1, ks + 2); }
        cp_commit();
    }

    // ---- epilogue: warp n-tile is entirely in one output half ----
    const int gid = lane >> 2, tig = lane & 3;
    if (wn < 128) {
        #pragma unroll
        for (int mf = 0; mf < 4; ++mf) {
            int r = m0 + wm + mf * 16 + gid;
            #pragma unroll
            for (int nf = 0; nf < 8; ++nf) {
                int col = wn + nf * 8 + tig * 2;
                *(__half2*)&Yn[(size_t)r * 128 + col] =
                    __floats2half2_rn(acc[mf][nf][0], acc[mf][nf][1]);
                *(__half2*)&Yn[(size_t)(r + 8) * 128 + col] =
                    __floats2half2_rn(acc[mf][nf][2], acc[mf][nf][3]);
            }
        }
    } else {
        #pragma unroll
        for (int mf = 0; mf < 4; ++mf) {
            int r = m0 + wm + mf * 16 + gid;
            #pragma unroll
            for (int nf = 0; nf < 8; ++nf) {
                int col = (wn - 128) + nf * 8 + tig * 2;
                *(float2*)&Ys[(size_t)r * 128 + col] =
                    make_float2(acc[mf][nf][0], acc[mf][nf][1]);
                *(float2*)&Ys[(size_t)(r + 8) * 128 + col] =
                    make_float2(acc[mf][nf][2], acc[mf][nf][3]);
            }
        }
    }
}

// ---------------- fused aggregation + epilogue ----------------
// Half-warp (16 lanes) per node, uint4 per lane, 4 edges in flight.
template<int DOUT, int RELU, int OUTBF>
__global__ void k_agg(const __half* __restrict__ Yn, const float* __restrict__ Ys,
                      const float* __restrict__ bias,
                      __nv_bfloat16* __restrict__ oh, __nv_bfloat16* __restrict__ ol,
                      float* __restrict__ of)
{
    int node = (int)((blockIdx.x * blockDim.x + threadIdx.x) >> 4);
    int l = threadIdx.x & 15;
    if (node >= N_NODES) return;
    int beg = g_rowptr[node];
    int cnt = g_rowcnt[node];
    const int c = l * 8;

    float s[8];
    #pragma unroll
    for (int t = 0; t < 8; ++t) s[t] = 0.f;

    int j = 0;
    for (; j + 4 <= cnt; j += 4) {
        int i0 = g_csr[beg + j];
        int i1 = g_csr[beg + j + 1];
        int i2 = g_csr[beg + j + 2];
        int i3 = g_csr[beg + j + 3];
        uint4 u0 = *(const uint4*)(Yn + (size_t)i0 * 128 + c);
        uint4 u1 = *(const uint4*)(Yn + (size_t)i1 * 128 + c);
        uint4 u2 = *(const uint4*)(Yn + (size_t)i2 * 128 + c);
        uint4 u3 = *(const uint4*)(Yn + (size_t)i3 * 128 + c);
        const __half2* h0 = (const __half2*)&u0;
        const __half2* h1 = (const __half2*)&u1;
        const __half2* h2 = (const __half2*)&u2;
        const __half2* h3 = (const __half2*)&u3;
        #pragma unroll
        for (int q = 0; q < 4; ++q) {
            float2 f0 = __half22float2(h0[q]);
            float2 f1 = __half22float2(h1[q]);
            float2 f2 = __half22float2(h2[q]);
            float2 f3 = __half22float2(h3[q]);
            s[2 * q]     += (f0.x + f1.x) + (f2.x + f3.x);
            s[2 * q + 1] += (f0.y + f1.y) + (f2.y + f3.y);
        }
    }
    for (; j < cnt; ++j) {
        int i0 = g_csr[beg + j];
        uint4 u0 = *(const uint4*)(Yn + (size_t)i0 * 128 + c);
        const __half2* h0 = (const __half2*)&u0;
        #pragma unroll
        for (int q = 0; q < 4; ++q) {
            float2 f0 = __half22float2(h0[q]);
            s[2 * q]     += f0.x;
            s[2 * q + 1] += f0.y;
        }
    }

    float inv = g_invdeg[node];
    float4 self0 = *(const float4*)(Ys + (size_t)node * 128 + c);
    float4 self1 = *(const float4*)(Ys + (size_t)node * 128 + c + 4);
    float selfv[8] = { self0.x, self0.y, self0.z, self0.w,
                       self1.x, self1.y, self1.z, self1.w };
    float v[8];
    #pragma unroll
    for (int t = 0; t < 8; ++t) {
        int cc = c + t;
        if (cc < DOUT) {
            float x = selfv[t] + s[t] * inv + bias[cc];
            v[t] = RELU ? fmaxf(x, 0.f) : x;
        } else {
            v[t] = 0.f;
        }
    }

    if (OUTBF) {
        union { __nv_bfloat162 b2[4]; uint4 u; } uh, ul;
        #pragma unroll
        for (int q = 0; q < 4; ++q) {
            __nv_bfloat16 h0, l0, h1, l1;
            split_bf(v[2 * q], h0, l0);
            split_bf(v[2 * q + 1], h1, l1);
            uh.b2[q] = __nv_bfloat162(h0, h1);
            ul.b2[q] = __nv_bfloat162(l0, l1);
        }
        *(uint4*)(oh + (size_t)node * 128 + c) = uh.u;
        *(uint4*)(ol + (size_t)node * 128 + c) = ul.u;
    } else {
        if (c < 104) {
            *(float4*)(of + (size_t)node * 104 + c) =
                make_float4(v[0], v[1], v[2], v[3]);
            *(float4*)(of + (size_t)node * 104 + c + 4) =
                make_float4(v[4], v[5], v[6], v[7]);
        }
    }
}

// ---------------- layer 4: tiny GEMM (N=10) + agg ----------------
__global__ void k_gemm4(const float* __restrict__ h3,
                        const float* __restrict__ ws4, const float* __restrict__ wn4,
                        float* __restrict__ hs4, float* __restrict__ hn4)
{
    __shared__ float sW[1040];
    int tid = threadIdx.x;
    for (int idx = tid; idx < 1040; idx += 256) {
        int k = idx / 10, cc = idx % 10;
        sW[idx] = (k < 103) ? ((cc < 5) ? ws4[k * 5 + cc] : wn4[k * 5 + (cc - 5)]) : 0.f;
    }
    __syncthreads();
    int node = blockIdx.x * 16 + (tid >> 4);
    int cc = tid & 15;
    if (node >= N_NODES || cc >= 10) return;
    const float4* row = (const float4*)(h3 + (size_t)node * 104);
    float acc = 0.f;
    #pragma unroll 13
    for (int kc = 0; kc < 26; ++kc) {
        float4 r = __ldg(row + kc);
        int kb = kc * 40;
        acc += r.x * sW[kb + cc] + r.y * sW[kb + 10 + cc]
             + r.z * sW[kb + 20 + cc] + r.w * sW[kb + 30 + cc];
    }
    if (cc < 5) hs4[node * 8 + cc] = acc;
    else        hn4[node * 8 + (cc - 5)] = acc;
}

__global__ void k_agg4(const float* __restrict__ hn4, const float* __restrict__ hs4,
                       const float* __restrict__ b4, float* __restrict__ h4)
{
    int n = blockIdx.x * blockDim.x + threadIdx.x;
    if (n >= N_NODES) return;
    int beg = g_rowptr[n], cnt = g_rowcnt[n];
    float a0 = 0.f, a1 = 0.f, a2 = 0.f, a3 = 0.f, a4 = 0.f;
    for (int j = 0; j < cnt; ++j) {
        const float* r = hn4 + (size_t)g_csr[beg + j] * 8;
        a0 += __ldg(r + 0); a1 += __ldg(r + 1); a2 += __ldg(r + 2);
        a3 += __ldg(r + 3); a4 += __ldg(r + 4);
    }
    float inv = g_invdeg[n];
    h4[n * 8 + 0] = hs4[n * 8 + 0] + inv * a0 + b4[0];
    h4[n * 8 + 1] = hs4[n * 8 + 1] + inv * a1 + b4[1];
    h4[n * 8 + 2] = hs4[n * 8 + 2] + inv * a2 + b4[2];
    h4[n * 8 + 3] = hs4[n * 8 + 3] + inv * a3 + b4[3];
    h4[n * 8 + 4] = hs4[n * 8 + 4] + inv * a4 + b4[4];
}

// ---------------- graph mean pooling ----------------
__global__ void k_pool(const float* __restrict__ h4, const int* __restrict__ gids) {
    int n = blockIdx.x * blockDim.x + threadIdx.x;
    if (n >= N_NODES) return;
    int g = gids[n];
    atomicAdd(&g_gcnt[g], 1);
    #pragma unroll
    for (int cc = 0; cc < 5; ++cc)
        atomicAdd(&g_pool[g * 5 + cc], h4[n * 8 + cc]);
}

__global__ void k_final(float* __restrict__ out) {
    int i = blockIdx.x * blockDim.x + threadIdx.x;
    if (i < N_GRAPHS * 5) {
        int g = i / 5;
        int c = g_gcnt[g];
        out[i] = g_pool[i] / (float)(c > 0 ? c : 1);
    }
}

// ---------------- launch ----------------
extern "C" void kernel_launch(void* const* d_in, const int* in_sizes, int n_in,
                              void* d_out, int out_size)
{
    const float* in_feat = (const float*)d_in[0];
    const int*   src     = (const int*)d_in[1];
    const int*   dst     = (const int*)d_in[2];
    const int*   gids    = (const int*)d_in[3];
    const float* ws[4] = { (const float*)d_in[4],  (const float*)d_in[7],
                           (const float*)d_in[10], (const float*)d_in[13] };
    const float* wn[4] = { (const float*)d_in[5],  (const float*)d_in[8],
                           (const float*)d_in[11], (const float*)d_in[14] };
    const float* bs[4] = { (const float*)d_in[6],  (const float*)d_in[9],
                           (const float*)d_in[12], (const float*)d_in[15] };

    __nv_bfloat16 *ah, *al, *bh, *bl;
    __half* yn;
    float *ys, *h3, *h4;
    cudaGetSymbolAddress((void**)&ah, g_ah);
    cudaGetSymbolAddress((void**)&al, g_al);
    cudaGetSymbolAddress((void**)&bh, g_bh);
    cudaGetSymbolAddress((void**)&bl, g_bl);
    cudaGetSymbolAddress((void**)&yn, g_yn);
    cudaGetSymbolAddress((void**)&ys, g_ys);
    cudaGetSymbolAddress((void**)&h3, g_h3);
    cudaGetSymbolAddress((void**)&h4, g_h4);
    float* hs4 = ys;                 // g_ys free after agg3
    float* hn4 = ys + 800000;

    cudaFuncSetAttribute(k_gemm_pipe, cudaFuncAttributeMaxDynamicSharedMemorySize, GEMM_SMEM);

    const int TB = 256;
    const int gemmGrid = N_PAD / 128;               // 782
    const int aggBlocks = (N_NODES * 16 + TB - 1) / TB;   // half-warp per node

    k_zero<<<(N_NODES + TB - 1) / TB, TB>>>();                               // 0
    k_wconv<<<128, TB>>>(wn[0], ws[0], 128, 128);                            // 1
    k_conv_in<<<(N_PAD * 128) / TB, TB>>>(in_feat);                          // 2
    k_gemm_pipe<<<gemmGrid, TB, GEMM_SMEM>>>(ah, al, bh, bl, yn, ys);        // 3 (profiled)
    k_count<<<(N_EDGES + TB - 1) / TB, TB>>>(dst);                           // 4
    k_scan1<<<NB_SCAN, SCAN_B>>>();                                          // 5
    k_scan2<<<1, 128>>>();                                                   // 6
    k_scan3<<<NB_SCAN, SCAN_B>>>();                                          // 7
    k_fill<<<(N_EDGES + TB - 1) / TB, TB>>>(src, dst);                       // 8

    // layer 1 epilogue -> bf16 planes for layer 2
    k_agg<128, 1, 1><<<aggBlocks, TB>>>(yn, ys, bs[0], ah, al, nullptr);     // 9
    // layer 2
    k_wconv<<<128, TB>>>(wn[1], ws[1], 128, 118);                            // 10
    k_gemm_pipe<<<gemmGrid, TB, GEMM_SMEM>>>(ah, al, bh, bl, yn, ys);        // 11
    k_agg<118, 1, 1><<<aggBlocks, TB>>>(yn, ys, bs[1], ah, al, nullptr);     // 12
    // layer 3
    k_wconv<<<128, TB>>>(wn[2], ws[2], 118, 103);                            // 13
    k_gemm_pipe<<<gemmGrid, TB, GEMM_SMEM>>>(ah, al, bh, bl, yn, ys);        // 14
    k_agg<103, 1, 0><<<aggBlocks, TB>>>(yn, ys, bs[2], nullptr, nullptr, h3);// 15
    // layer 4 (SIMT, tiny)
    k_gemm4<<<(N_NODES + 15) / 16, TB>>>(h3, ws[3], wn[3], hs4, hn4);        // 16
    k_agg4<<<(N_NODES + TB - 1) / TB, TB>>>(hn4, hs4, bs[3], h4);            // 17
    // pooling
    k_pool<<<(N_NODES + TB - 1) / TB, TB>>>(h4, gids);                       // 18
    k_final<<<1, 512>>>((float*)d_out);                                      // 19
}

// round 8
// speedup vs baseline: 1.2075x; 1.2075x over previous
#include <cuda_runtime.h>
#include <cuda_bf16.h>
#include <cuda_fp16.h>
#include <cstdint>

#define N_NODES  100000
#define N_PAD    100096          // 782 * 128
#define N_EDGES  1600000
#define N_GRAPHS 100
#define SCAN_B   1024
#define NB_SCAN  98

// ---------------- scratch (static __device__ allocations only) ----------------
__device__ __half g_a [N_PAD * 128];          // activations, fp16, pitch 128
__device__ __half g_bh[256 * 128];            // B hi plane [n][k] fp16
__device__ __half g_bl[256 * 128];            // B lo plane (fp16 residual)
__device__ __half g_yn[N_PAD * 128];          // neighbor-transform out (fp16)
__device__ float  g_ys[N_PAD * 128];          // self-transform out (fp32)
__device__ float  g_h3[N_NODES * 104];        // layer-3 activation (fp32, pitch 104)
__device__ float  g_h4[N_NODES * 8];          // final node features (pitch 8)
__device__ float g_invdeg[N_NODES];
__device__ int   g_rowcnt[N_NODES];
__device__ int   g_rowptr[N_NODES];
__device__ int   g_cursor[N_NODES];
__device__ int   g_csr[N_EDGES];
__device__ int   g_bsum[128];
__device__ int   g_boff[128];
__device__ float g_pool[N_GRAPHS * 5];
__device__ int   g_gcnt[N_GRAPHS];

// ---------------- PTX helpers ----------------
__device__ __forceinline__ uint32_t smem_u32(const void* p) {
    uint32_t a;
    asm("{ .reg .u64 t; cvta.to.shared.u64 t, %1; cvt.u32.u64 %0, t; }" : "=r"(a) : "l"(p));
    return a;
}
__device__ __forceinline__ void ldsm4(uint32_t* r, uint32_t addr) {
    asm volatile("ldmatrix.sync.aligned.m8n8.x4.shared.b16 {%0,%1,%2,%3}, [%4];"
                 : "=r"(r[0]), "=r"(r[1]), "=r"(r[2]), "=r"(r[3]) : "r"(addr));
}
__device__ __forceinline__ void mma16816h(float* c, const uint32_t* a,
                                          uint32_t b0, uint32_t b1) {
    asm volatile(
        "mma.sync.aligned.m16n8k16.row.col.f32.f16.f16.f32 "
        "{%0,%1,%2,%3}, {%4,%5,%6,%7}, {%8,%9}, {%0,%1,%2,%3};"
        : "+f"(c[0]), "+f"(c[1]), "+f"(c[2]), "+f"(c[3])
        : "r"(a[0]), "r"(a[1]), "r"(a[2]), "r"(a[3]), "r"(b0), "r"(b1));
}
__device__ __forceinline__ void cpa16(uint32_t d, const void* g) {
    asm volatile("cp.async.cg.shared.global [%0], [%1], 16;" :: "r"(d), "l"(g));
}
__device__ __forceinline__ void cp_commit() {
    asm volatile("cp.async.commit_group;" ::: "memory");
}
template<int N> __device__ __forceinline__ void cp_wait() {
    asm volatile("cp.async.wait_group %0;" :: "n"(N) : "memory");
}

// ---------------- CSR build ----------------
__global__ void k_zero() {
    int i = blockIdx.x * blockDim.x + threadIdx.x;
    if (i < N_NODES) g_rowcnt[i] = 0;
    if (i < N_GRAPHS * 5) g_pool[i] = 0.f;
    if (i < N_GRAPHS) g_gcnt[i] = 0;
}

__global__ void k_count(const int* __restrict__ dst) {
    int e = blockIdx.x * blockDim.x + threadIdx.x;
    if (e < N_EDGES) atomicAdd(&g_rowcnt[dst[e]], 1);
}

__global__ void k_scan1() {
    __shared__ int s[SCAN_B];
    int tid = threadIdx.x;
    int gid = blockIdx.x * SCAN_B + tid;
    int v = (gid < N_NODES) ? g_rowcnt[gid] : 0;
    s[tid] = v;
    __syncthreads();
    for (int off = 1; off < SCAN_B; off <<= 1) {
        int t = (tid >= off) ? s[tid - off] : 0;
        __syncthreads();
        s[tid] += t;
        __syncthreads();
    }
    if (gid < N_NODES) g_rowptr[gid] = s[tid] - v;
    if (tid == SCAN_B - 1) g_bsum[blockIdx.x] = s[tid];
}

__global__ void k_scan2() {
    __shared__ int s[128];
    int t = threadIdx.x;
    int v = (t < NB_SCAN) ? g_bsum[t] : 0;
    s[t] = v;
    __syncthreads();
    for (int off = 1; off < 128; off <<= 1) {
        int x = (t >= off) ? s[t - off] : 0;
        __syncthreads();
        s[t] += x;
        __syncthreads();
    }
    if (t < NB_SCAN) g_boff[t] = s[t] - v;
}

__global__ void k_scan3() {
    int gid = blockIdx.x * SCAN_B + threadIdx.x;
    if (gid < N_NODES) {
        int rp = g_rowptr[gid] + g_boff[blockIdx.x];
        g_rowptr[gid] = rp;
        g_cursor[gid] = rp;
        int c = g_rowcnt[gid];
        g_invdeg[gid] = 1.0f / (float)(c > 0 ? c : 1);
    }
}

__global__ void k_fill(const int* __restrict__ src, const int* __restrict__ dst) {
    int e = blockIdx.x * blockDim.x + threadIdx.x;
    if (e < N_EDGES) {
        int pos = atomicAdd(&g_cursor[dst[e]], 1);
        g_csr[pos] = src[e];
    }
}

// ---------------- input / weight conversion ----------------
__device__ __forceinline__ void split_h(float v, __half& h, __half& l) {
    h = __float2half(v);
    l = __float2half(v - __half2float(h));
}

__global__ void k_conv_in(const float* __restrict__ x) {
    int idx = blockIdx.x * blockDim.x + threadIdx.x;   // N_PAD*128
    int n = idx >> 7;
    float v = (n < N_NODES) ? x[idx] : 0.f;
    g_a[idx] = __float2half(v);
}

// B[n][k] = Wn[k][n] (n<128) | Ws[k][n-128], zero-padded; fp16 hi + residual lo
__global__ void k_wconv(const float* __restrict__ Wn, const float* __restrict__ Ws,
                        int K, int dout) {
    int idx = blockIdx.x * blockDim.x + threadIdx.x;   // 256*128
    int n = idx >> 7, k = idx & 127;
    float v = 0.f;
    if (k < K) {
        if (n < 128) { if (n < dout) v = Wn[k * dout + n]; }
        else { int s = n - 128; if (s < dout) v = Ws[k * dout + s]; }
    }
    __half h, l;
    split_h(v, h, l);
    g_bh[idx] = h;
    g_bl[idx] = l;
}

// ---------------- pipelined HMMA GEMM (fp16 2-product) ----------------
// Per CTA: 128(m) x 128(n), K=128 in 4 chunks of 32, 2-stage cp.async.
// blockIdx.y = 0: B rows [0,128) (Wn) -> Yn fp16;  = 1: B rows [128,256) -> Ys fp32.
// C = A * (Bh + Bl): 2 MMA products, A single fp16 plane.
#define PITCH  80
#define PLANE  10240
#define STAGEB 30720                     // A + Bh + Bl
#define GEMM_SMEM 61440

__global__ void __launch_bounds__(256, 2)
k_gemm_pipe(const __half* __restrict__ a,
            const __half* __restrict__ bh, const __half* __restrict__ bl,
            __half* __restrict__ Yn, float* __restrict__ Ys)
{
    extern __shared__ char smem[];
    const int tid = threadIdx.x;
    const int m0 = blockIdx.x * 128;
    const int n0 = blockIdx.y * 128;
    const uint32_t sb = smem_u32(smem);

    const int f_row = tid >> 2;          // 64 rows per pass
    const int f_kc  = tid & 3;
    #define FILL(st, ks) do {                                                  \
        uint32_t sbase = sb + (st) * STAGEB;                                   \
        _Pragma("unroll")                                                      \
        for (int i = 0; i < 2; ++i) {                                          \
            int row = f_row + i * 64;                                          \
            uint32_t doff = row * PITCH + f_kc * 16;                           \
            size_t ga = (size_t)(m0 + row) * 128 + (ks) * 32 + f_kc * 8;       \
            size_t gb = (size_t)(n0 + row) * 128 + (ks) * 32 + f_kc * 8;       \
            cpa16(sbase + doff,             a  + ga);                          \
            cpa16(sbase + PLANE + doff,     bh + gb);                          \
            cpa16(sbase + 2 * PLANE + doff, bl + gb);                          \
        }                                                                      \
    } while (0)

    FILL(0, 0); cp_commit();
    FILL(1, 1); cp_commit();

    const int wid = tid >> 5, lane = tid & 31;
    const int wm  = (wid & 1) * 64;
    const int wn2 = (wid >> 1) * 32;

    float acc[4][4][4];
    #pragma unroll
    for (int mf = 0; mf < 4; ++mf)
        #pragma unroll
        for (int nf = 0; nf < 4; ++nf)
            #pragma unroll
            for (int q = 0; q < 4; ++q) acc[mf][nf][q] = 0.f;

    const uint32_t aL = (uint32_t)(lane & 15) * PITCH + (lane >> 4) * 16;
    const uint32_t bL = (uint32_t)((lane & 7) + ((lane >> 4) << 3)) * PITCH
                        + ((lane >> 3) & 1) * 16;

    #pragma unroll
    for (int ks = 0; ks < 4; ++ks) {
        cp_wait<1>();
        __syncthreads();
        const uint32_t st = sb + (ks & 1) * STAGEB;
        #pragma unroll
        for (int kk = 0; kk < 2; ++kk) {
            const uint32_t kb = kk * 32;
            uint32_t A4[4][4], Bh4[2][4], Bl4[2][4];
            #pragma unroll
            for (int mf = 0; mf < 4; ++mf)
                ldsm4(A4[mf], st + (uint32_t)(wm + mf * 16) * PITCH + aL + kb);
            #pragma unroll
            for (int nq = 0; nq < 2; ++nq) {
                uint32_t bbase = st + PLANE + (uint32_t)(wn2 + nq * 16) * PITCH + bL + kb;
                ldsm4(Bh4[nq], bbase);
                ldsm4(Bl4[nq], bbase + PLANE);
            }
            #pragma unroll
            for (int nq = 0; nq < 2; ++nq)
                #pragma unroll
                for (int mf = 0; mf < 4; ++mf) {
                    float* c0 = acc[mf][2 * nq];
                    float* c1 = acc[mf][2 * nq + 1];
                    mma16816h(c0, A4[mf], Bh4[nq][0], Bh4[nq][1]);
                    mma16816h(c0, A4[mf], Bl4[nq][0], Bl4[nq][1]);
                    mma16816h(c1, A4[mf], Bh4[nq][2], Bh4[nq][3]);
                    mma16816h(c1, A4[mf], Bl4[nq][2], Bl4[nq][3]);
                }
        }
        __syncthreads();
        if (ks + 2 < 4) FILL(ks & 1, ks + 2);
        cp_commit();
    }

    // ---- epilogue ----
    const int gid = lane >> 2, tig = lane & 3;
    if (blockIdx.y == 0) {
        #pragma unroll
        for (int mf = 0; mf < 4; ++mf) {
            int r = m0 + wm + mf * 16 + gid;
            #pragma unroll
            for (int nf = 0; nf < 4; ++nf) {
                int col = wn2 + nf * 8 + tig * 2;
                *(__half2*)&Yn[(size_t)r * 128 + col] =
                    __floats2half2_rn(acc[mf][nf][0], acc[mf][nf][1]);
                *(__half2*)&Yn[(size_t)(r + 8) * 128 + col] =
                    __floats2half2_rn(acc[mf][nf][2], acc[mf][nf][3]);
            }
        }
    } else {
        #pragma unroll
        for (int mf = 0; mf < 4; ++mf) {
            int r = m0 + wm + mf * 16 + gid;
            #pragma unroll
            for (int nf = 0; nf < 4; ++nf) {
                int col = wn2 + nf * 8 + tig * 2;
                *(float2*)&Ys[(size_t)r * 128 + col] =
                    make_float2(acc[mf][nf][0], acc[mf][nf][1]);
                *(float2*)&Ys[(size_t)(r + 8) * 128 + col] =
                    make_float2(acc[mf][nf][2], acc[mf][nf][3]);
            }
        }
    }
}

// ---------------- fused aggregation + epilogue ----------------
// Half-warp (16 lanes) per node, uint4 per lane.
// OUTH=1: write fp16 activation plane (pitch 128, zero-padded); else fp32 pitch 104.
template<int DOUT, int RELU, int OUTH>
__global__ void k_agg(const __half* __restrict__ Yn, const float* __restrict__ Ys,
                      const float* __restrict__ bias,
                      __half* __restrict__ oh, float* __restrict__ of)
{
    int node = (int)((blockIdx.x * blockDim.x + threadIdx.x) >> 4);
    int l = threadIdx.x & 15;
    if (node >= N_NODES) return;
    int beg = g_rowptr[node];
    int cnt = g_rowcnt[node];
    const int c = l * 8;

    float s[8];
    #pragma unroll
    for (int t = 0; t < 8; ++t) s[t] = 0.f;

    int j = 0;
    for (; j + 2 <= cnt; j += 2) {
        int i0 = g_csr[beg + j];
        int i1 = g_csr[beg + j + 1];
        uint4 u0 = *(const uint4*)(Yn + (size_t)i0 * 128 + c);
        uint4 u1 = *(const uint4*)(Yn + (size_t)i1 * 128 + c);
        const __half2* h0 = (const __half2*)&u0;
        const __half2* h1 = (const __half2*)&u1;
        #pragma unroll
        for (int q = 0; q < 4; ++q) {
            float2 f0 = __half22float2(h0[q]);
            float2 f1 = __half22float2(h1[q]);
            s[2 * q]     += f0.x + f1.x;
            s[2 * q + 1] += f0.y + f1.y;
        }
    }
    if (j < cnt) {
        int i0 = g_csr[beg + j];
        uint4 u0 = *(const uint4*)(Yn + (size_t)i0 * 128 + c);
        const __half2* h0 = (const __half2*)&u0;
        #pragma unroll
        for (int q = 0; q < 4; ++q) {
            float2 f0 = __half22float2(h0[q]);
            s[2 * q]     += f0.x;
            s[2 * q + 1] += f0.y;
        }
    }

    float inv = g_invdeg[node];
    float4 self0 = *(const float4*)(Ys + (size_t)node * 128 + c);
    float4 self1 = *(const float4*)(Ys + (size_t)node * 128 + c + 4);
    float selfv[8] = { self0.x, self0.y, self0.z, self0.w,
                       self1.x, self1.y, self1.z, self1.w };
    float v[8];
    #pragma unroll
    for (int t = 0; t < 8; ++t) {
        int cc = c + t;
        if (cc < DOUT) {
            float x = selfv[t] + s[t] * inv + bias[cc];
            v[t] = RELU ? fmaxf(x, 0.f) : x;
        } else {
            v[t] = 0.f;
        }
    }

    if (OUTH) {
        union { __half2 h2[4]; uint4 u; } uo;
        #pragma unroll
        for (int q = 0; q < 4; ++q)
            uo.h2[q] = __floats2half2_rn(v[2 * q], v[2 * q + 1]);
        *(uint4*)(oh + (size_t)node * 128 + c) = uo.u;
    } else {
        if (c < 104) {
            *(float4*)(of + (size_t)node * 104 + c) =
                make_float4(v[0], v[1], v[2], v[3]);
            *(float4*)(of + (size_t)node * 104 + c + 4) =
                make_float4(v[4], v[5], v[6], v[7]);
        }
    }
}

// ---------------- layer 4: tiny GEMM (N=10) + agg ----------------
__global__ void k_gemm4(const float* __restrict__ h3,
                        const float* __restrict__ ws4, const float* __restrict__ wn4,
                        float* __restrict__ hs4, float* __restrict__ hn4)
{
    __shared__ float sW[1040];
    int tid = threadIdx.x;
    for (int idx = tid; idx < 1040; idx += 256) {
        int k = idx / 10, cc = idx % 10;
        sW[idx] = (k < 103) ? ((cc < 5) ? ws4[k * 5 + cc] : wn4[k * 5 + (cc - 5)]) : 0.f;
    }
    __syncthreads();
    int node = blockIdx.x * 16 + (tid >> 4);
    int cc = tid & 15;
    if (node >= N_NODES || cc >= 10) return;
    const float4* row = (const float4*)(h3 + (size_t)node * 104);
    float acc = 0.f;
    #pragma unroll 13
    for (int kc = 0; kc < 26; ++kc) {
        float4 r = __ldg(row + kc);
        int kb = kc * 40;
        acc += r.x * sW[kb + cc] + r.y * sW[kb + 10 + cc]
             + r.z * sW[kb + 20 + cc] + r.w * sW[kb + 30 + cc];
    }
    if (cc < 5) hs4[node * 8 + cc] = acc;
    else        hn4[node * 8 + (cc - 5)] = acc;
}

__global__ void k_agg4(const float* __restrict__ hn4, const float* __restrict__ hs4,
                       const float* __restrict__ b4, float* __restrict__ h4)
{
    int n = blockIdx.x * blockDim.x + threadIdx.x;
    if (n >= N_NODES) return;
    int beg = g_rowptr[n], cnt = g_rowcnt[n];
    float a0 = 0.f, a1 = 0.f, a2 = 0.f, a3 = 0.f, a4 = 0.f;
    for (int j = 0; j < cnt; ++j) {
        const float* r = hn4 + (size_t)g_csr[beg + j] * 8;
        a0 += __ldg(r + 0); a1 += __ldg(r + 1); a2 += __ldg(r + 2);
        a3 += __ldg(r + 3); a4 += __ldg(r + 4);
    }
    float inv = g_invdeg[n];
    h4[n * 8 + 0] = hs4[n * 8 + 0] + inv * a0 + b4[0];
    h4[n * 8 + 1] = hs4[n * 8 + 1] + inv * a1 + b4[1];
    h4[n * 8 + 2] = hs4[n * 8 + 2] + inv * a2 + b4[2];
    h4[n * 8 + 3] = hs4[n * 8 + 3] + inv * a3 + b4[3];
    h4[n * 8 + 4] = hs4[n * 8 + 4] + inv * a4 + b4[4];
}

// ---------------- graph mean pooling ----------------
__global__ void k_pool(const float* __restrict__ h4, const int* __restrict__ gids) {
    int n = blockIdx.x * blockDim.x + threadIdx.x;
    if (n >= N_NODES) return;
    int g = gids[n];
    atomicAdd(&g_gcnt[g], 1);
    #pragma unroll
    for (int cc = 0; cc < 5; ++cc)
        atomicAdd(&g_pool[g * 5 + cc], h4[n * 8 + cc]);
}

__global__ void k_final(float* __restrict__ out) {
    int i = blockIdx.x * blockDim.x + threadIdx.x;
    if (i < N_GRAPHS * 5) {
        int g = i / 5;
        int c = g_gcnt[g];
        out[i] = g_pool[i] / (float)(c > 0 ? c : 1);
    }
}

// ---------------- launch ----------------
extern "C" void kernel_launch(void* const* d_in, const int* in_sizes, int n_in,
                              void* d_out, int out_size)
{
    const float* in_feat = (const float*)d_in[0];
    const int*   src     = (const int*)d_in[1];
    const int*   dst     = (const int*)d_in[2];
    const int*   gids    = (const int*)d_in[3];
    const float* ws[4] = { (const float*)d_in[4],  (const float*)d_in[7],
                           (const float*)d_in[10], (const float*)d_in[13] };
    const float* wn[4] = { (const float*)d_in[5],  (const float*)d_in[8],
                           (const float*)d_in[11], (const float*)d_in[14] };
    const float* bs[4] = { (const float*)d_in[6],  (const float*)d_in[9],
                           (const float*)d_in[12], (const float*)d_in[15] };

    __half *a, *bh, *bl, *yn;
    float *ys, *h3, *h4;
    cudaGetSymbolAddress((void**)&a,  g_a);
    cudaGetSymbolAddress((void**)&bh, g_bh);
    cudaGetSymbolAddress((void**)&bl, g_bl);
    cudaGetSymbolAddress((void**)&yn, g_yn);
    cudaGetSymbolAddress((void**)&ys, g_ys);
    cudaGetSymbolAddress((void**)&h3, g_h3);
    cudaGetSymbolAddress((void**)&h4, g_h4);
    float* hs4 = ys;                 // g_ys free after agg3
    float* hn4 = ys + 800000;

    cudaFuncSetAttribute(k_gemm_pipe, cudaFuncAttributeMaxDynamicSharedMemorySize, GEMM_SMEM);

    const int TB = 256;
    const dim3 gemmGrid(N_PAD / 128, 2);                  // 782 x 2
    const int aggBlocks = (N_NODES * 16 + TB - 1) / TB;   // half-warp per node

    k_zero<<<(N_NODES + TB - 1) / TB, TB>>>();                               // 0
    k_wconv<<<128, TB>>>(wn[0], ws[0], 128, 128);                            // 1
    k_conv_in<<<(N_PAD * 128) / TB, TB>>>(in_feat);                          // 2
    k_gemm_pipe<<<gemmGrid, TB, GEMM_SMEM>>>(a, bh, bl, yn, ys);             // 3 (profiled)
    k_count<<<(N_EDGES + TB - 1) / TB, TB>>>(dst);                           // 4
    k_scan1<<<NB_SCAN, SCAN_B>>>();                                          // 5
    k_scan2<<<1, 128>>>();                                                   // 6
    k_scan3<<<NB_SCAN, SCAN_B>>>();                                          // 7
    k_fill<<<(N_EDGES + TB - 1) / TB, TB>>>(src, dst);                       // 8

    // layer 1 epilogue -> fp16 activations for layer 2
    k_agg<128, 1, 1><<<aggBlocks, TB>>>(yn, ys, bs[0], a, nullptr);          // 9
    // layer 2
    k_wconv<<<128, TB>>>(wn[1], ws[1], 128, 118);                            // 10
    k_gemm_pipe<<<gemmGrid, TB, GEMM_SMEM>>>(a, bh, bl, yn, ys);             // 11
    k_agg<118, 1, 1><<<aggBlocks, TB>>>(yn, ys, bs[1], a, nullptr);          // 12
    // layer 3
    k_wconv<<<128, TB>>>(wn[2], ws[2], 118, 103);                            // 13
    k_gemm_pipe<<<gemmGrid, TB, GEMM_SMEM>>>(a, bh, bl, yn, ys);             // 14
    k_agg<103, 1, 0><<<aggBlocks, TB>>>(yn, ys, bs[2], nullptr, h3);         // 15
    // layer 4 (SIMT, tiny)
    k_gemm4<<<(N_NODES + 15) / 16, TB>>>(h3, ws[3], wn[3], hs4, hn4);        // 16
    k_agg4<<<(N_NODES + TB - 1) / TB, TB>>>(hn4, hs4, bs[3], h4);            // 17
    // pooling
    k_pool<<<(N_NODES + TB - 1) / TB, TB>>>(h4, gids);                       // 18
    k_final<<<1, 512>>>((float*)d_out);                                      // 19
}